// round 9
// baseline (speedup 1.0000x reference)
#include <cuda_runtime.h>
#include <math.h>
#include <stdint.h>

#define Bq 32
#define Vq 2048
#define Pq 64
#define Aq 8
#define Fq 72          // P + A
#define NFq 128
#define TWOF 144       // 2*F
#define NPC 64         // partial slots per batch (= 16 chunks * 4 subsets)

// Scratch (device globals; no allocation allowed)
__device__ float    g_agg  [Bq * Vq * Aq];             // 2.1 MB
__device__ uint32_t g_MT   [Bq * NFq * Aq];            // M transposed, tf32
__device__ uint32_t g_W12T [Fq * 64];                  // [n][k] tf32 (W1|W2)^T
__device__ uint32_t g_WoutT[NFq * 64];                 // [n][k] tf32 Wout_top^T
__device__ float    g_pmax [Bq * NPC * Aq * Fq];
__device__ float    g_psum [Bq * NPC * Aq * Fq];

__device__ __forceinline__ uint32_t f2tf32(float f) {
    uint32_t r; asm("cvt.rna.tf32.f32 %0, %1;" : "=r"(r) : "f"(f)); return r;
}
__device__ __forceinline__ void mma_tf32(float* d, const uint32_t* a, const uint32_t* b) {
    asm("mma.sync.aligned.m16n8k8.row.col.f32.tf32.tf32.f32 "
        "{%0,%1,%2,%3},{%4,%5,%6,%7},{%8,%9},{%0,%1,%2,%3};"
        : "+f"(d[0]), "+f"(d[1]), "+f"(d[2]), "+f"(d[3])
        : "r"(a[0]), "r"(a[1]), "r"(a[2]), "r"(a[3]), "r"(b[0]), "r"(b[1]));
}
__device__ __forceinline__ uint32_t s2u(const void* p) {
    return (uint32_t)__cvta_generic_to_shared(p);
}
__device__ __forceinline__ void ldsm4(uint32_t* r, uint32_t addr) {
    asm volatile("ldmatrix.sync.aligned.m8n8.x4.shared.b16 {%0,%1,%2,%3}, [%4];"
                 : "=r"(r[0]), "=r"(r[1]), "=r"(r[2]), "=r"(r[3]) : "r"(addr));
}
__device__ __forceinline__ void ldsm2(uint32_t* r, uint32_t addr) {
    asm volatile("ldmatrix.sync.aligned.m8n8.x2.shared.b16 {%0,%1}, [%2];"
                 : "=r"(r[0]), "=r"(r[1]) : "r"(addr));
}
__device__ __forceinline__ float ftanh(float x) {
    float e = __expf(2.0f * x);
    return 1.0f - __fdividef(2.0f, e + 1.0f);
}
__device__ __forceinline__ void cpasync16(uint32_t dst, const void* src) {
    asm volatile("cp.async.cg.shared.global [%0], [%1], 16;" :: "r"(dst), "l"(src));
}
__device__ __forceinline__ void cpasync_wait() {
    asm volatile("cp.async.commit_group;");
    asm volatile("cp.async.wait_group 0;");
}

// ---------------------------------------------------------------------------
// kT: one-time transpose + tf32 conversion of weights.
// ---------------------------------------------------------------------------
__global__ void __launch_bounds__(256)
kT(const float* __restrict__ W1, const float* __restrict__ W2,
   const float* __restrict__ Wout) {
    const int i = blockIdx.x * 256 + threadIdx.x;    // grid 32 -> 8192 threads
    if (i < Fq * 64) {                               // W12T
        int n = i >> 6, k = i & 63;
        float v = (n < Pq) ? W1[k * Pq + n] : W2[k * Aq + (n - Pq)];
        g_W12T[i] = f2tf32(v);
    }
    {                                                // WoutT (8192 elements)
        int n = i >> 6, k = i & 63;
        g_WoutT[i] = f2tf32(Wout[k * NFq + n]);
    }
}

// ---------------------------------------------------------------------------
// k1: per 128-row tile: feats = [X@W1+b1 | exp(-|X@W2+b2|)] via tf32 MMA into
// smem (aliased over Xs), then 4-subset partial max/sum of agg[v,a]*feats[v,f].
// 576 threads = 18 warps. MMA: warps 0-15 (8 row-groups x 2 n-groups).
// Reduce: 4 v-subsets of 32 x (8 a x 18 f4).
// ---------------------------------------------------------------------------
#define XS1 68         // tf32 word stride of Xs / Wt rows
#define SFS 80         // float stride of feats tile
__global__ void __launch_bounds__(576)
k1(const float* __restrict__ X,
   const float* __restrict__ b1, const float* __restrict__ b2) {
    extern __shared__ uint32_t smu[];
    uint32_t* Wt = smu;                     // [72][68] tf32, rows=n, cols=k
    uint32_t* Xs = Wt + Fq * XS1;           // [128][68] tf32 (aliased with sf)
    float*    sf = (float*)Xs;              // [128][80] feats (after MMA)
    float*    bs = (float*)(Xs + 128 * SFS);// [72]

    const int tid = threadIdx.x;
    const long row0 = (long)blockIdx.x * 128;
    const int b = blockIdx.x >> 4, chunk = blockIdx.x & 15;

    // Wt via cp.async (pre-transposed, pre-converted)
    for (int i = tid; i < Fq * 16; i += 576) {
        int n = i >> 4, c = i & 15;
        cpasync16(s2u(Wt + n * XS1 + c * 4), g_W12T + n * 64 + c * 4);
    }
    // X tile: batch 4 LDG.128 in flight, then convert + store
    {
        float4 v[4]; int idx[4]; int cnt = 0;
#pragma unroll
        for (int j = 0; j < 4; j++) {
            int i = tid + j * 576;
            if (i < 128 * 16) {
                int r = i >> 4, c = i & 15;
                v[cnt] = *(const float4*)(X + (row0 + r) * Pq + c * 4);
                idx[cnt] = i; cnt++;
            }
        }
#pragma unroll
        for (int j = 0; j < 4; j++) {
            if (j < cnt) {
                int r = idx[j] >> 4, c = idx[j] & 15;
                uint32_t* d = Xs + r * XS1 + c * 4;
                d[0] = f2tf32(v[j].x); d[1] = f2tf32(v[j].y);
                d[2] = f2tf32(v[j].z); d[3] = f2tf32(v[j].w);
            }
        }
    }
    if (tid < Fq) bs[tid] = (tid < Pq) ? b1[tid] : b2[tid - Pq];
    cpasync_wait();
    __syncthreads();

    const int wid = tid >> 5, lane = tid & 31;
    const int lq = lane & 3, lg = lane >> 2;

    float d[5][4];
    int rg = 0, wg = 0;

    if (wid < 16) {
        rg = wid & 7;            // row group: rows rg*16..+15
        wg = wid >> 3;           // n group: 0 -> nt 0..4, 1 -> nt 5..8

        const int rA = lane & 15;
        const int cA = (lane & 16) >> 2;
        const int rB = (lane & 7) + ((lane & 16) >> 1);
        const int cB = (lane & 8) >> 1;

        uint32_t aAddr = s2u(Xs + (rg * 16 + rA) * XS1 + cA);

#pragma unroll
        for (int nt = 0; nt < 5; nt++)
#pragma unroll
            for (int r = 0; r < 4; r++) d[nt][r] = 0.f;

        if (wg == 0) {
            uint32_t b0 = s2u(Wt + (0  + rB) * XS1 + cB);
            uint32_t b1a = s2u(Wt + (16 + rB) * XS1 + cB);
            uint32_t b2a = s2u(Wt + (32 + (lane & 7)) * XS1 + cB);
#pragma unroll
            for (int ks = 0; ks < 8; ks++) {
                uint32_t a[4];
                ldsm4(a, aAddr); aAddr += 32;
                uint32_t bf[5][2];
                ldsm4(&bf[0][0], b0);  b0  += 32;
                ldsm4(&bf[2][0], b1a); b1a += 32;
                ldsm2(bf[4], b2a);     b2a += 32;
#pragma unroll
                for (int nt = 0; nt < 5; nt++) mma_tf32(d[nt], a, bf[nt]);
            }
        } else {
            uint32_t b0 = s2u(Wt + (40 + rB) * XS1 + cB);
            uint32_t b1a = s2u(Wt + (56 + rB) * XS1 + cB);
#pragma unroll
            for (int ks = 0; ks < 8; ks++) {
                uint32_t a[4];
                ldsm4(a, aAddr); aAddr += 32;
                uint32_t bf[4][2];
                ldsm4(&bf[0][0], b0);  b0  += 32;
                ldsm4(&bf[2][0], b1a); b1a += 32;
#pragma unroll
                for (int nt = 0; nt < 4; nt++) mma_tf32(d[nt], a, bf[nt]);
            }
        }
    }
    __syncthreads();   // all Xs reads done; safe to overwrite with sf

    if (wid < 16) {
        const int orow = rg * 16 + lg;
        if (wg == 0) {
#pragma unroll
            for (int nt = 0; nt < 5; nt++) {
                const int col = nt * 8 + 2 * lq;
                *(float2*)&sf[orow * SFS + col] =
                    make_float2(d[nt][0] + bs[col], d[nt][1] + bs[col + 1]);
                *(float2*)&sf[(orow + 8) * SFS + col] =
                    make_float2(d[nt][2] + bs[col], d[nt][3] + bs[col + 1]);
            }
        } else {
#pragma unroll
            for (int nt = 0; nt < 3; nt++) {
                const int col = (nt + 5) * 8 + 2 * lq;
                *(float2*)&sf[orow * SFS + col] =
                    make_float2(d[nt][0] + bs[col], d[nt][1] + bs[col + 1]);
                *(float2*)&sf[(orow + 8) * SFS + col] =
                    make_float2(d[nt][2] + bs[col], d[nt][3] + bs[col + 1]);
            }
            {   // nt local 3 = global 8 -> agg cols 64..71
                const int col = 64 + 2 * lq;
                float e0 = __expf(-fabsf(d[3][0] + bs[col]));
                float e1 = __expf(-fabsf(d[3][1] + bs[col + 1]));
                float e2 = __expf(-fabsf(d[3][2] + bs[col]));
                float e3 = __expf(-fabsf(d[3][3] + bs[col + 1]));
                *(float2*)&sf[orow * SFS + col]       = make_float2(e0, e1);
                *(float2*)&sf[(orow + 8) * SFS + col] = make_float2(e2, e3);
                *(float2*)(g_agg + (row0 + orow) * Aq + 2 * lq)     = make_float2(e0, e1);
                *(float2*)(g_agg + (row0 + orow + 8) * Aq + 2 * lq) = make_float2(e2, e3);
            }
        }
    }
    __syncthreads();

    // partial reduce: 4 subsets of 32 v; thread -> (a, f4 quad)
    {
        const int sub = tid / 144;       // 0..3
        const int t   = tid % 144;
        const int a8  = t & 7;
        const int f4  = t >> 3;          // 0..17 -> f cols f4*4..+3
        const int vbase = sub * 32;

        float4 mx = make_float4(-INFINITY, -INFINITY, -INFINITY, -INFINITY);
        float4 sv = make_float4(0.f, 0.f, 0.f, 0.f);
#pragma unroll 8
        for (int i = 0; i < 32; i++) {
            const int v = vbase + i;
            float e = sf[v * SFS + 64 + a8];
            float4 x = *(float4*)&sf[v * SFS + f4 * 4];
            float p0 = e * x.x, p1 = e * x.y, p2 = e * x.z, p3 = e * x.w;
            mx.x = fmaxf(mx.x, p0); mx.y = fmaxf(mx.y, p1);
            mx.z = fmaxf(mx.z, p2); mx.w = fmaxf(mx.w, p3);
            sv.x += p0; sv.y += p1; sv.z += p2; sv.w += p3;
        }
        const int pc = chunk * 4 + sub;
        const long o = (((long)b * NPC + pc) * Aq + a8) * Fq + f4 * 4;
        *(float4*)(g_pmax + o) = mx;
        *(float4*)(g_psum + o) = sv;
    }
}

// ---------------------------------------------------------------------------
// kB2: combine partials -> collapsed[a,2F]; MT[b,n,a] = (collapsed@Wout_mid + direct)^T
// ---------------------------------------------------------------------------
__global__ void __launch_bounds__(576)
kB2(const float* __restrict__ Wout) {
    const int b = blockIdx.x;
    const int tid = threadIdx.x;
    const int a = tid % Aq;
    const int f = tid / Aq;

    __shared__ float scol[Aq][TWOF];

    {
        float vmax = -INFINITY, vsum = 0.f;
        const long base = ((long)b * NPC) * Aq * Fq + a * Fq + f;
#pragma unroll 8
        for (int pc = 0; pc < NPC; pc++) {
            vmax = fmaxf(vmax, g_pmax[base + (long)pc * Aq * Fq]);
            vsum += g_psum[base + (long)pc * Aq * Fq];
        }
        scol[a][f]      = vmax;
        scol[a][Fq + f] = vsum * (1.0f / (float)Vq);
    }
    __syncthreads();

    for (int idx = tid; idx < Aq * NFq; idx += 576) {
        int aa = idx / NFq, n = idx % NFq;
        float acc = Wout[(Pq + Aq * TWOF + aa) * NFq + n];   // agg direct term
#pragma unroll 16
        for (int g = 0; g < TWOF; g++) {
            acc = fmaf(scol[aa][g], Wout[(Pq + aa * TWOF + g) * NFq + n], acc);
        }
        g_MT[((long)b * NFq + n) * Aq + aa] = f2tf32(acc);
    }
}

// ---------------------------------------------------------------------------
// k3: out = tanh( [X | agg] @ [Wout_top ; M_b] + bout ) via tf32 MMA + ldmatrix
// BM=64, N=128, K=72. 256 threads = 8 warps (2m x 4n), warp tile m32 x n32.
// smem ~57.5 KB -> 3 CTAs/SM.
// ---------------------------------------------------------------------------
#define XS3 76
__global__ void __launch_bounds__(256, 3)
k3(const float* __restrict__ X, const float* __restrict__ bout,
   float* __restrict__ out) {
    extern __shared__ uint32_t sm3[];
    uint32_t* Xs = sm3;                   // [64][76] tf32: cols 0-63 X, 64-71 agg
    uint32_t* Wt = Xs + 64 * XS3;         // [128][76] tf32: rows n, cols k (0..71)
    float*    bs = (float*)(Wt + 128 * XS3);  // [128]

    const int tid = threadIdx.x;
    const long row0 = (long)blockIdx.x * 64;
    const int b = blockIdx.x >> 5;

    // Wt rows via cp.async from pre-converted globals
    for (int i = tid; i < 128 * 18; i += 256) {
        int n = i / 18, s = i % 18;
        const void* src = (s < 16) ? (const void*)(g_WoutT + n * 64 + s * 4)
                                   : (const void*)(g_MT + ((long)b * NFq + n) * Aq + (s - 16) * 4);
        cpasync16(s2u(Wt + n * XS3 + s * 4), src);
    }
    // X: batch 4 LDG.128, then convert + store
    {
        float4 v[4];
#pragma unroll
        for (int j = 0; j < 4; j++) {
            int i = tid + j * 256;
            int r = i >> 4, c = i & 15;
            v[j] = *(const float4*)(X + (row0 + r) * Pq + c * 4);
        }
#pragma unroll
        for (int j = 0; j < 4; j++) {
            int i = tid + j * 256;
            int r = i >> 4, c = i & 15;
            uint32_t* d = Xs + r * XS3 + c * 4;
            d[0] = f2tf32(v[j].x); d[1] = f2tf32(v[j].y);
            d[2] = f2tf32(v[j].z); d[3] = f2tf32(v[j].w);
        }
    }
    if (tid < 64 * 2) {
        int r = tid >> 1, c = tid & 1;
        float4 v = *(const float4*)(g_agg + (row0 + r) * Aq + c * 4);
        uint32_t* d = Xs + r * XS3 + Pq + c * 4;
        d[0] = f2tf32(v.x); d[1] = f2tf32(v.y); d[2] = f2tf32(v.z); d[3] = f2tf32(v.w);
    }
    if (tid < NFq) bs[tid] = bout[tid];
    cpasync_wait();
    __syncthreads();

    const int wid = tid >> 5, lane = tid & 31;
    const int wm = wid >> 2, wn = wid & 3;     // 2 x 4 warps, m32 x n32 tiles
    const int lq = lane & 3, lg = lane >> 2;

    const int rA = lane & 15;
    const int cA = (lane & 16) >> 2;
    const int rB = (lane & 7) + ((lane & 16) >> 1);
    const int cB = (lane & 8) >> 1;

    uint32_t aAddr[2], bAddr[2];
#pragma unroll
    for (int mt = 0; mt < 2; mt++)
        aAddr[mt] = s2u(Xs + (wm * 32 + mt * 16 + rA) * XS3 + cA);
#pragma unroll
    for (int p = 0; p < 2; p++)
        bAddr[p] = s2u(Wt + (wn * 32 + p * 16 + rB) * XS3 + cB);

    float d[2][4][4];
#pragma unroll
    for (int mt = 0; mt < 2; mt++)
#pragma unroll
        for (int nt = 0; nt < 4; nt++)
#pragma unroll
            for (int r = 0; r < 4; r++) d[mt][nt][r] = 0.f;

#pragma unroll
    for (int ks = 0; ks < 9; ks++) {
        uint32_t a[2][4];
#pragma unroll
        for (int mt = 0; mt < 2; mt++) {
            ldsm4(a[mt], aAddr[mt]); aAddr[mt] += 32;
        }
        uint32_t bf[4][2];
#pragma unroll
        for (int p = 0; p < 2; p++) {
            ldsm4(&bf[2 * p][0], bAddr[p]); bAddr[p] += 32;
        }
#pragma unroll
        for (int mt = 0; mt < 2; mt++)
#pragma unroll
            for (int nt = 0; nt < 4; nt++)
                mma_tf32(d[mt][nt], a[mt], bf[nt]);
    }

#pragma unroll
    for (int mt = 0; mt < 2; mt++) {
        const long r0 = row0 + wm * 32 + mt * 16 + lg;
#pragma unroll
        for (int nt = 0; nt < 4; nt++) {
            const int c0 = wn * 32 + nt * 8 + 2 * lq;
            float2 o0, o1;
            o0.x = ftanh(d[mt][nt][0] + bs[c0]);
            o0.y = ftanh(d[mt][nt][1] + bs[c0 + 1]);
            o1.x = ftanh(d[mt][nt][2] + bs[c0]);
            o1.y = ftanh(d[mt][nt][3] + bs[c0 + 1]);
            *(float2*)(out + (r0)     * NFq + c0) = o0;
            *(float2*)(out + (r0 + 8) * NFq + c0) = o1;
        }
    }
}

// ---------------------------------------------------------------------------
extern "C" void kernel_launch(void* const* d_in, const int* in_sizes, int n_in,
                              void* d_out, int out_size) {
    const float* X    = (const float*)d_in[0];
    const float* W1   = (const float*)d_in[1];
    const float* b1   = (const float*)d_in[2];
    const float* W2   = (const float*)d_in[3];
    const float* b2   = (const float*)d_in[4];
    const float* Wout = (const float*)d_in[5];
    const float* bout = (const float*)d_in[6];
    float* out = (float*)d_out;

    const int smem1 = (Fq * XS1 + 128 * SFS) * 4 + Fq * 4;     // ~60.8 KB
    const int smem3 = (64 * XS3 + 128 * XS3) * 4 + NFq * 4;    // ~57.5 KB
    cudaFuncSetAttribute(k1, cudaFuncAttributeMaxDynamicSharedMemorySize, smem1);
    cudaFuncSetAttribute(k3, cudaFuncAttributeMaxDynamicSharedMemorySize, smem3);

    kT<<<32, 256>>>(W1, W2, Wout);

    k1<<<(Bq * Vq) / 128, 576, smem1>>>(X, b1, b2);

    kB2<<<Bq, 576>>>(Wout);

    k3<<<(Bq * Vq) / 64, 256, smem3>>>(X, bout, out);
}

// round 10
// speedup vs baseline: 1.0384x; 1.0384x over previous
#include <cuda_runtime.h>
#include <math.h>
#include <stdint.h>

#define Bq 32
#define Vq 2048
#define Pq 64
#define Aq 8
#define Fq 72          // P + A
#define NFq 128
#define TWOF 144       // 2*F
#define NPC 64         // partial slots per batch (= 16 chunks * 4 subsets)

// Scratch (device globals; no allocation allowed)
__device__ float    g_agg  [Bq * Vq * Aq];             // 2.1 MB
__device__ uint32_t g_MT   [Bq * NFq * Aq];            // M transposed, tf32
__device__ uint32_t g_W12T [Fq * 64];                  // [n][k] tf32 (W1|W2)^T
__device__ uint32_t g_WoutT[NFq * 64];                 // [n][k] tf32 Wout_top^T
__device__ float    g_pmax [Bq * NPC * Aq * Fq];
__device__ float    g_psum [Bq * NPC * Aq * Fq];

__device__ __forceinline__ uint32_t f2tf32(float f) {
    uint32_t r; asm("cvt.rna.tf32.f32 %0, %1;" : "=r"(r) : "f"(f)); return r;
}
__device__ __forceinline__ void mma_tf32(float* d, const uint32_t* a, const uint32_t* b) {
    asm("mma.sync.aligned.m16n8k8.row.col.f32.tf32.tf32.f32 "
        "{%0,%1,%2,%3},{%4,%5,%6,%7},{%8,%9},{%0,%1,%2,%3};"
        : "+f"(d[0]), "+f"(d[1]), "+f"(d[2]), "+f"(d[3])
        : "r"(a[0]), "r"(a[1]), "r"(a[2]), "r"(a[3]), "r"(b[0]), "r"(b[1]));
}
__device__ __forceinline__ uint32_t s2u(const void* p) {
    return (uint32_t)__cvta_generic_to_shared(p);
}
__device__ __forceinline__ void ldsm4(uint32_t* r, uint32_t addr) {
    asm volatile("ldmatrix.sync.aligned.m8n8.x4.shared.b16 {%0,%1,%2,%3}, [%4];"
                 : "=r"(r[0]), "=r"(r[1]), "=r"(r[2]), "=r"(r[3]) : "r"(addr));
}
__device__ __forceinline__ void ldsm2(uint32_t* r, uint32_t addr) {
    asm volatile("ldmatrix.sync.aligned.m8n8.x2.shared.b16 {%0,%1}, [%2];"
                 : "=r"(r[0]), "=r"(r[1]) : "r"(addr));
}
__device__ __forceinline__ float ftanh(float x) {
    float e = __expf(2.0f * x);
    return 1.0f - __fdividef(2.0f, e + 1.0f);
}
__device__ __forceinline__ void cpasync16(uint32_t dst, const void* src) {
    asm volatile("cp.async.cg.shared.global [%0], [%1], 16;" :: "r"(dst), "l"(src));
}
__device__ __forceinline__ void cpasync_wait() {
    asm volatile("cp.async.commit_group;");
    asm volatile("cp.async.wait_group 0;");
}

// ---------------------------------------------------------------------------
// kT: one-time transpose + tf32 conversion of weights.
// ---------------------------------------------------------------------------
__global__ void __launch_bounds__(256)
kT(const float* __restrict__ W1, const float* __restrict__ W2,
   const float* __restrict__ Wout) {
    const int i = blockIdx.x * 256 + threadIdx.x;    // grid 32 -> 8192 threads
    if (i < Fq * 64) {                               // W12T
        int n = i >> 6, k = i & 63;
        float v = (n < Pq) ? W1[k * Pq + n] : W2[k * Aq + (n - Pq)];
        g_W12T[i] = f2tf32(v);
    }
    {                                                // WoutT (8192 elements)
        int n = i >> 6, k = i & 63;
        g_WoutT[i] = f2tf32(Wout[k * NFq + n]);
    }
}

// ---------------------------------------------------------------------------
// k1: per 128-row tile: feats = [X@W1+b1 | exp(-|X@W2+b2|)] via tf32 MMA into
// smem (aliased over Xs), then 4-subset partial max/sum of agg[v,a]*feats[v,f].
// 576 threads = 18 warps. MMA: warps 0-15 (8 row-groups x 2 n-groups).
// ---------------------------------------------------------------------------
#define XS1 68         // tf32 word stride of Xs / Wt rows
#define SFS 80         // float stride of feats tile
__global__ void __launch_bounds__(576)
k1(const float* __restrict__ X,
   const float* __restrict__ b1, const float* __restrict__ b2) {
    extern __shared__ uint32_t smu[];
    uint32_t* Wt = smu;                     // [72][68] tf32, rows=n, cols=k
    uint32_t* Xs = Wt + Fq * XS1;           // [128][68] tf32 (aliased with sf)
    float*    sf = (float*)Xs;              // [128][80] feats (after MMA)
    float*    bs = (float*)(Xs + 128 * SFS);// [72]

    const int tid = threadIdx.x;
    const long row0 = (long)blockIdx.x * 128;
    const int b = blockIdx.x >> 4, chunk = blockIdx.x & 15;

    // Wt via cp.async (pre-transposed, pre-converted)
    for (int i = tid; i < Fq * 16; i += 576) {
        int n = i >> 4, c = i & 15;
        cpasync16(s2u(Wt + n * XS1 + c * 4), g_W12T + n * 64 + c * 4);
    }
    // X tile: batch 4 LDG.128 in flight, then convert + store
    {
        float4 v[4]; int idx[4]; int cnt = 0;
#pragma unroll
        for (int j = 0; j < 4; j++) {
            int i = tid + j * 576;
            if (i < 128 * 16) {
                int r = i >> 4, c = i & 15;
                v[cnt] = *(const float4*)(X + (row0 + r) * Pq + c * 4);
                idx[cnt] = i; cnt++;
            }
        }
#pragma unroll
        for (int j = 0; j < 4; j++) {
            if (j < cnt) {
                int r = idx[j] >> 4, c = idx[j] & 15;
                uint32_t* d = Xs + r * XS1 + c * 4;
                d[0] = f2tf32(v[j].x); d[1] = f2tf32(v[j].y);
                d[2] = f2tf32(v[j].z); d[3] = f2tf32(v[j].w);
            }
        }
    }
    if (tid < Fq) bs[tid] = (tid < Pq) ? b1[tid] : b2[tid - Pq];
    cpasync_wait();
    __syncthreads();

    const int wid = tid >> 5, lane = tid & 31;
    const int lq = lane & 3, lg = lane >> 2;

    float d[5][4];
    int rg = 0, wg = 0;

    if (wid < 16) {
        rg = wid & 7;            // row group: rows rg*16..+15
        wg = wid >> 3;           // n group: 0 -> nt 0..4, 1 -> nt 5..8

        const int rA = lane & 15;
        const int cA = (lane & 16) >> 2;
        const int rB = (lane & 7) + ((lane & 16) >> 1);
        const int cB = (lane & 8) >> 1;

        uint32_t aAddr = s2u(Xs + (rg * 16 + rA) * XS1 + cA);

#pragma unroll
        for (int nt = 0; nt < 5; nt++)
#pragma unroll
            for (int r = 0; r < 4; r++) d[nt][r] = 0.f;

        if (wg == 0) {
            uint32_t b0 = s2u(Wt + (0  + rB) * XS1 + cB);
            uint32_t b1a = s2u(Wt + (16 + rB) * XS1 + cB);
            uint32_t b2a = s2u(Wt + (32 + (lane & 7)) * XS1 + cB);
#pragma unroll
            for (int ks = 0; ks < 8; ks++) {
                uint32_t a[4];
                ldsm4(a, aAddr); aAddr += 32;
                uint32_t bf[5][2];
                ldsm4(&bf[0][0], b0);  b0  += 32;
                ldsm4(&bf[2][0], b1a); b1a += 32;
                ldsm2(bf[4], b2a);     b2a += 32;
#pragma unroll
                for (int nt = 0; nt < 5; nt++) mma_tf32(d[nt], a, bf[nt]);
            }
        } else {
            uint32_t b0 = s2u(Wt + (40 + rB) * XS1 + cB);
            uint32_t b1a = s2u(Wt + (56 + rB) * XS1 + cB);
#pragma unroll
            for (int ks = 0; ks < 8; ks++) {
                uint32_t a[4];
                ldsm4(a, aAddr); aAddr += 32;
                uint32_t bf[4][2];
                ldsm4(&bf[0][0], b0);  b0  += 32;
                ldsm4(&bf[2][0], b1a); b1a += 32;
#pragma unroll
                for (int nt = 0; nt < 4; nt++) mma_tf32(d[nt], a, bf[nt]);
            }
        }
    }
    __syncthreads();   // all Xs reads done; safe to overwrite with sf

    if (wid < 16) {
        const int orow = rg * 16 + lg;
        if (wg == 0) {
#pragma unroll
            for (int nt = 0; nt < 5; nt++) {
                const int col = nt * 8 + 2 * lq;
                *(float2*)&sf[orow * SFS + col] =
                    make_float2(d[nt][0] + bs[col], d[nt][1] + bs[col + 1]);
                *(float2*)&sf[(orow + 8) * SFS + col] =
                    make_float2(d[nt][2] + bs[col], d[nt][3] + bs[col + 1]);
            }
        } else {
#pragma unroll
            for (int nt = 0; nt < 3; nt++) {
                const int col = (nt + 5) * 8 + 2 * lq;
                *(float2*)&sf[orow * SFS + col] =
                    make_float2(d[nt][0] + bs[col], d[nt][1] + bs[col + 1]);
                *(float2*)&sf[(orow + 8) * SFS + col] =
                    make_float2(d[nt][2] + bs[col], d[nt][3] + bs[col + 1]);
            }
            {   // nt local 3 = global 8 -> agg cols 64..71
                const int col = 64 + 2 * lq;
                float e0 = __expf(-fabsf(d[3][0] + bs[col]));
                float e1 = __expf(-fabsf(d[3][1] + bs[col + 1]));
                float e2 = __expf(-fabsf(d[3][2] + bs[col]));
                float e3 = __expf(-fabsf(d[3][3] + bs[col + 1]));
                *(float2*)&sf[orow * SFS + col]       = make_float2(e0, e1);
                *(float2*)&sf[(orow + 8) * SFS + col] = make_float2(e2, e3);
                *(float2*)(g_agg + (row0 + orow) * Aq + 2 * lq)     = make_float2(e0, e1);
                *(float2*)(g_agg + (row0 + orow + 8) * Aq + 2 * lq) = make_float2(e2, e3);
            }
        }
    }
    __syncthreads();

    // partial reduce: 4 subsets of 32 v; thread -> (a, f4 quad)
    {
        const int sub = tid / 144;       // 0..3
        const int t   = tid % 144;
        const int a8  = t & 7;
        const int f4  = t >> 3;          // 0..17 -> f cols f4*4..+3
        const int vbase = sub * 32;

        float4 mx = make_float4(-INFINITY, -INFINITY, -INFINITY, -INFINITY);
        float4 sv = make_float4(0.f, 0.f, 0.f, 0.f);
#pragma unroll 8
        for (int i = 0; i < 32; i++) {
            const int v = vbase + i;
            float e = sf[v * SFS + 64 + a8];
            float4 x = *(float4*)&sf[v * SFS + f4 * 4];
            float p0 = e * x.x, p1 = e * x.y, p2 = e * x.z, p3 = e * x.w;
            mx.x = fmaxf(mx.x, p0); mx.y = fmaxf(mx.y, p1);
            mx.z = fmaxf(mx.z, p2); mx.w = fmaxf(mx.w, p3);
            sv.x += p0; sv.y += p1; sv.z += p2; sv.w += p3;
        }
        const int pc = chunk * 4 + sub;
        const long o = (((long)b * NPC + pc) * Aq + a8) * Fq + f4 * 4;
        *(float4*)(g_pmax + o) = mx;
        *(float4*)(g_psum + o) = sv;
    }
}

// ---------------------------------------------------------------------------
// kB2: combine partials -> collapsed[a,2F]; MT[b,n,a] = (collapsed@Wout_mid + direct)^T
// ---------------------------------------------------------------------------
__global__ void __launch_bounds__(576)
kB2(const float* __restrict__ Wout) {
    const int b = blockIdx.x;
    const int tid = threadIdx.x;
    const int a = tid % Aq;
    const int f = tid / Aq;

    __shared__ float scol[Aq][TWOF];

    {
        float vmax = -INFINITY, vsum = 0.f;
        const long base = ((long)b * NPC) * Aq * Fq + a * Fq + f;
#pragma unroll 8
        for (int pc = 0; pc < NPC; pc++) {
            vmax = fmaxf(vmax, g_pmax[base + (long)pc * Aq * Fq]);
            vsum += g_psum[base + (long)pc * Aq * Fq];
        }
        scol[a][f]      = vmax;
        scol[a][Fq + f] = vsum * (1.0f / (float)Vq);
    }
    __syncthreads();

    for (int idx = tid; idx < Aq * NFq; idx += 576) {
        int aa = idx / NFq, n = idx % NFq;
        float acc = Wout[(Pq + Aq * TWOF + aa) * NFq + n];   // agg direct term
#pragma unroll 16
        for (int g = 0; g < TWOF; g++) {
            acc = fmaf(scol[aa][g], Wout[(Pq + aa * TWOF + g) * NFq + n], acc);
        }
        g_MT[((long)b * NFq + n) * Aq + aa] = f2tf32(acc);
    }
}

// ---------------------------------------------------------------------------
// k3: out = tanh( [X | agg] @ [Wout_top ; M_b] + bout ) via tf32 MMA + ldmatrix
// BM=128, N=128, K=72. 512 threads = 16 warps (4m x 4n), warp tile m32 x n32.
// (round-8 shape: best measured k3)
// ---------------------------------------------------------------------------
#define XS3 76
__global__ void __launch_bounds__(512)
k3(const float* __restrict__ X, const float* __restrict__ bout,
   float* __restrict__ out) {
    extern __shared__ uint32_t sm3[];
    uint32_t* Xs = sm3;                   // [128][76] tf32: cols 0-63 X, 64-71 agg
    uint32_t* Wt = Xs + 128 * XS3;        // [128][76] tf32: rows n, cols k (0..71)
    float*    bs = (float*)(Wt + 128 * XS3);  // [128]

    const int tid = threadIdx.x;
    const long row0 = (long)blockIdx.x * 128;
    const int b = blockIdx.x >> 4;

    // Wt rows via cp.async from pre-converted globals
    for (int i = tid; i < 128 * 18; i += 512) {
        int n = i / 18, s = i % 18;
        const void* src = (s < 16) ? (const void*)(g_WoutT + n * 64 + s * 4)
                                   : (const void*)(g_MT + ((long)b * NFq + n) * Aq + (s - 16) * 4);
        cpasync16(s2u(Wt + n * XS3 + s * 4), src);
    }
    // X: batch 4 LDG.128, then convert + store
    {
        float4 v[4];
#pragma unroll
        for (int j = 0; j < 4; j++) {
            int i = tid + j * 512;
            int r = i >> 4, c = i & 15;
            v[j] = *(const float4*)(X + (row0 + r) * Pq + c * 4);
        }
#pragma unroll
        for (int j = 0; j < 4; j++) {
            int i = tid + j * 512;
            int r = i >> 4, c = i & 15;
            uint32_t* d = Xs + r * XS3 + c * 4;
            d[0] = f2tf32(v[j].x); d[1] = f2tf32(v[j].y);
            d[2] = f2tf32(v[j].z); d[3] = f2tf32(v[j].w);
        }
    }
    if (tid < 128 * 2) {
        int r = tid >> 1, c = tid & 1;
        float4 v = *(const float4*)(g_agg + (row0 + r) * Aq + c * 4);
        uint32_t* d = Xs + r * XS3 + Pq + c * 4;
        d[0] = f2tf32(v.x); d[1] = f2tf32(v.y); d[2] = f2tf32(v.z); d[3] = f2tf32(v.w);
    }
    if (tid < NFq) bs[tid] = bout[tid];
    cpasync_wait();
    __syncthreads();

    const int wid = tid >> 5, lane = tid & 31;
    const int wm = wid >> 2, wn = wid & 3;     // 4 x 4 warps, m32 x n32 tiles
    const int lq = lane & 3, lg = lane >> 2;

    const int rA = lane & 15;
    const int cA = (lane & 16) >> 2;
    const int rB = (lane & 7) + ((lane & 16) >> 1);
    const int cB = (lane & 8) >> 1;

    uint32_t aAddr[2], bAddr[2];
#pragma unroll
    for (int mt = 0; mt < 2; mt++)
        aAddr[mt] = s2u(Xs + (wm * 32 + mt * 16 + rA) * XS3 + cA);
#pragma unroll
    for (int p = 0; p < 2; p++)
        bAddr[p] = s2u(Wt + (wn * 32 + p * 16 + rB) * XS3 + cB);

    float d[2][4][4];
#pragma unroll
    for (int mt = 0; mt < 2; mt++)
#pragma unroll
        for (int nt = 0; nt < 4; nt++)
#pragma unroll
            for (int r = 0; r < 4; r++) d[mt][nt][r] = 0.f;

#pragma unroll
    for (int ks = 0; ks < 9; ks++) {
        uint32_t a[2][4];
#pragma unroll
        for (int mt = 0; mt < 2; mt++) {
            ldsm4(a[mt], aAddr[mt]); aAddr[mt] += 32;
        }
        uint32_t bf[4][2];
#pragma unroll
        for (int p = 0; p < 2; p++) {
            ldsm4(&bf[2 * p][0], bAddr[p]); bAddr[p] += 32;
        }
#pragma unroll
        for (int mt = 0; mt < 2; mt++)
#pragma unroll
            for (int nt = 0; nt < 4; nt++)
                mma_tf32(d[mt][nt], a[mt], bf[nt]);
    }

#pragma unroll
    for (int mt = 0; mt < 2; mt++) {
        const long r0 = row0 + wm * 32 + mt * 16 + lg;
#pragma unroll
        for (int nt = 0; nt < 4; nt++) {
            const int c0 = wn * 32 + nt * 8 + 2 * lq;
            float2 o0, o1;
            o0.x = ftanh(d[mt][nt][0] + bs[c0]);
            o0.y = ftanh(d[mt][nt][1] + bs[c0 + 1]);
            o1.x = ftanh(d[mt][nt][2] + bs[c0]);
            o1.y = ftanh(d[mt][nt][3] + bs[c0 + 1]);
            *(float2*)(out + (r0)     * NFq + c0) = o0;
            *(float2*)(out + (r0 + 8) * NFq + c0) = o1;
        }
    }
}

// ---------------------------------------------------------------------------
extern "C" void kernel_launch(void* const* d_in, const int* in_sizes, int n_in,
                              void* d_out, int out_size) {
    const float* X    = (const float*)d_in[0];
    const float* W1   = (const float*)d_in[1];
    const float* b1   = (const float*)d_in[2];
    const float* W2   = (const float*)d_in[3];
    const float* b2   = (const float*)d_in[4];
    const float* Wout = (const float*)d_in[5];
    const float* bout = (const float*)d_in[6];
    float* out = (float*)d_out;

    const int smem1 = (Fq * XS1 + 128 * SFS) * 4 + Fq * 4;     // ~60.8 KB
    const int smem3 = (128 * XS3 * 2) * 4 + NFq * 4;           // ~78.3 KB
    cudaFuncSetAttribute(k1, cudaFuncAttributeMaxDynamicSharedMemorySize, smem1);
    cudaFuncSetAttribute(k3, cudaFuncAttributeMaxDynamicSharedMemorySize, smem3);

    kT<<<32, 256>>>(W1, W2, Wout);

    k1<<<(Bq * Vq) / 128, 576, smem1>>>(X, b1, b2);

    kB2<<<Bq, 576>>>(Wout);

    k3<<<(Bq * Vq) / 128, 512, smem3>>>(X, bout, out);
}